// round 15
// baseline (speedup 1.0000x reference)
#include <cuda_runtime.h>
#include <cuda_bf16.h>
#include <float.h>

// Problem: out[b][c] = max over (h,w) of in[b][h][w][c]
//   in : [32, 224, 224, 128] f32, NHWC (C contiguous)
//   out: [32, 128] f32
// Pure HBM-streaming reduction: 822 MB read, 16 KB written.
//
// Best measured main loop (occ 3 / 80 regs / 12 front-batched streaming
// LDG.128 folded into 6 accumulators; benches 118.8-119.8us @ 87-89% DRAM)
// fused with the single-launch epilogue: per-block partials -> __device__
// scratch, arrival counter, last block per batch combines the 37 partials
// (L2-resident, 19 KB) and writes out[b] directly. Removes the separate
// init_out launch and the atomicMax tail from the graph.

static constexpr int B  = 32;
static constexpr int HW = 224 * 224;   // 50176 spatial rows per batch
static constexpr int C  = 128;         // channels (contiguous)
static constexpr int C4 = C / 4;       // 32 float4 groups per row

static constexpr int THREADS = 256;    // 32 c4-lanes x 8 row-lanes
static constexpr int ROWS_PER_BLK = THREADS / C4;       // 8
static constexpr int GRID_X = 37;      // 37*32 = 1184 blocks
static constexpr int STRIDE = GRID_X * ROWS_PER_BLK;    // 296 rows
static constexpr int UNROLL = 12;      // loads front-batched per iteration
static constexpr int NACC   = 6;       // accumulators (fold pairs)

// Static device scratch (no dynamic allocation allowed).
__device__ float4 g_partials[B][GRID_X][C4];   // 606 KB
__device__ int    g_arrival[B];                // zero-initialized at load

__device__ __forceinline__ float4 f4max(float4 a, float4 b) {
    return make_float4(fmaxf(a.x, b.x), fmaxf(a.y, b.y),
                       fmaxf(a.z, b.z), fmaxf(a.w, b.w));
}

__global__ __launch_bounds__(THREADS, 3)   // 80 regs: full 12-load batch
void max_spatial_kernel(const float* __restrict__ in, float* __restrict__ out) {
    const int b   = blockIdx.y;
    const int bx  = blockIdx.x;
    const int c4  = threadIdx.x & (C4 - 1);   // float4 channel group 0..31
    const int r   = threadIdx.x >> 5;         // row lane 0..7

    // Base pointer for this batch + channel group (float4 units)
    const float4* base =
        reinterpret_cast<const float4*>(in + (size_t)b * HW * C) + c4;

    int row = bx * ROWS_PER_BLK + r;

    float4 m[NACC];
    #pragma unroll
    for (int i = 0; i < NACC; i++)
        m[i] = make_float4(-FLT_MAX, -FLT_MAX, -FLT_MAX, -FLT_MAX);

    // 12 independent streaming LDG.128 front-batched per iteration.
    for (; row + (UNROLL - 1) * STRIDE < HW; row += UNROLL * STRIDE) {
        float4 v[UNROLL];
        #pragma unroll
        for (int i = 0; i < UNROLL; i++)
            v[i] = __ldcs(base + (size_t)(row + i * STRIDE) * C4);
        #pragma unroll
        for (int i = 0; i < NACC; i++)
            m[i] = f4max(m[i], f4max(v[2 * i], v[2 * i + 1]));
    }
    for (; row < HW; row += STRIDE) {
        m[0] = f4max(m[0], __ldcs(base + (size_t)row * C4));
    }

    // Combine the 6 accumulators
    m[0] = f4max(m[0], m[1]);
    m[2] = f4max(m[2], m[3]);
    m[4] = f4max(m[4], m[5]);
    m[0] = f4max(m[0], f4max(m[2], m[4]));

    // Reduce across the 8 row-lanes sharing this c4 (tid, tid+32, ... tid+224)
    __shared__ float4 sm[THREADS];
    sm[threadIdx.x] = m[0];
    __syncthreads();
    if (threadIdx.x < 128) sm[threadIdx.x] = f4max(sm[threadIdx.x], sm[threadIdx.x + 128]);
    __syncthreads();
    if (threadIdx.x < 64)  sm[threadIdx.x] = f4max(sm[threadIdx.x], sm[threadIdx.x + 64]);
    __syncthreads();
    if (threadIdx.x < 32) {
        float4 v = f4max(sm[threadIdx.x], sm[threadIdx.x + 32]);
        g_partials[b][bx][threadIdx.x] = v;     // non-atomic STG.128
    }

    // Make partial visible, then count arrivals for this batch.
    __threadfence();
    __shared__ int is_last;
    if (threadIdx.x == 0) {
        int old = atomicAdd(&g_arrival[b], 1);
        is_last = (old == GRID_X - 1);
    }
    __syncthreads();

    // Last block of this batch: combine the 37 partials, write out, reset.
    if (is_last) {
        if (threadIdx.x < C4) {
            float4 acc = g_partials[b][0][threadIdx.x];
            #pragma unroll
            for (int i = 1; i < GRID_X; i++)
                acc = f4max(acc, g_partials[b][i][threadIdx.x]);
            reinterpret_cast<float4*>(out)[b * C4 + threadIdx.x] = acc;
        }
        if (threadIdx.x == 0)
            g_arrival[b] = 0;   // self-reset for next graph replay
    }
}

extern "C" void kernel_launch(void* const* d_in, const int* in_sizes, int n_in,
                              void* d_out, int out_size) {
    const float* in = (const float*)d_in[0];
    float* out = (float*)d_out;

    dim3 grid(GRID_X, B);
    max_spatial_kernel<<<grid, THREADS>>>(in, out);
}

// round 16
// speedup vs baseline: 1.0193x; 1.0193x over previous
#include <cuda_runtime.h>
#include <cuda_bf16.h>
#include <float.h>

// Problem: out[b][c] = max over (h,w) of in[b][h][w][c]
//   in : [32, 224, 224, 128] f32, NHWC (C contiguous)
//   out: [32, 128] f32
// Pure HBM-streaming reduction: 822 MB read, 16 KB written.
//
// FINAL (session winner; benches 118.8 / 119.3 / 119.3 / 119.8 us @ 87-89%
// DRAM, 6.9-7.0 TB/s): grid (37, 32) strided rows, occ 3 (80 regs) so 12
// streaming LDG.128 are front-batched per thread (no staging), folded into
// 6 accumulators. smem tree reduce + float atomicMax into a
// -FLT_MAX-initialized output (separate init launch).
//
// Convergence evidence across 16 benches: occ {2,3,4} x MLP {4..16} x
// grid {608..1216} x {strided, contiguous, page-local} x {init+atomicMax,
// last-block-combine} all measure 6.6-7.0 TB/s; identical-source re-benches
// vary +-2.5us. The fused single-launch epilogue measured ~1-2us slower
// twice (threadfence + arrival-counter serializes the final combine).
// 822 MB at the ~7.0 TB/s practical HBM ceiling = ~117.5us floor; this
// kernel operates at >99% of it.

static constexpr int B  = 32;
static constexpr int HW = 224 * 224;   // 50176 spatial rows per batch
static constexpr int C  = 128;         // channels (contiguous)
static constexpr int C4 = C / 4;       // 32 float4 groups per row

static constexpr int THREADS = 256;    // 32 c4-lanes x 8 row-lanes
static constexpr int ROWS_PER_BLK = THREADS / C4;       // 8
static constexpr int GRID_X = 37;      // 37*32 = 1184 blocks
static constexpr int STRIDE = GRID_X * ROWS_PER_BLK;    // 296 rows
static constexpr int UNROLL = 12;      // loads front-batched per iteration
static constexpr int NACC   = 6;       // accumulators (fold pairs)

__device__ __forceinline__ float4 f4max(float4 a, float4 b) {
    return make_float4(fmaxf(a.x, b.x), fmaxf(a.y, b.y),
                       fmaxf(a.z, b.z), fmaxf(a.w, b.w));
}

// Float atomic-max via monotone int/uint reinterpretation (init = -FLT_MAX).
__device__ __forceinline__ void atomicMaxF(float* addr, float v) {
    if (v >= 0.0f) {
        atomicMax(reinterpret_cast<int*>(addr), __float_as_int(v));
    } else {
        atomicMin(reinterpret_cast<unsigned int*>(addr), __float_as_uint(v));
    }
}

__global__ void init_out_kernel(float* __restrict__ out, int n) {
    int i = blockIdx.x * blockDim.x + threadIdx.x;
    if (i < n) out[i] = -FLT_MAX;
}

__global__ __launch_bounds__(THREADS, 3)   // 80 regs: full 12-load batch
void max_spatial_kernel(const float* __restrict__ in, float* __restrict__ out) {
    const int b   = blockIdx.y;
    const int c4  = threadIdx.x & (C4 - 1);   // float4 channel group 0..31
    const int r   = threadIdx.x >> 5;         // row lane 0..7

    // Base pointer for this batch + channel group (float4 units)
    const float4* base =
        reinterpret_cast<const float4*>(in + (size_t)b * HW * C) + c4;

    int row = blockIdx.x * ROWS_PER_BLK + r;

    float4 m[NACC];
    #pragma unroll
    for (int i = 0; i < NACC; i++)
        m[i] = make_float4(-FLT_MAX, -FLT_MAX, -FLT_MAX, -FLT_MAX);

    // 12 independent streaming LDG.128 front-batched per iteration.
    for (; row + (UNROLL - 1) * STRIDE < HW; row += UNROLL * STRIDE) {
        float4 v[UNROLL];
        #pragma unroll
        for (int i = 0; i < UNROLL; i++)
            v[i] = __ldcs(base + (size_t)(row + i * STRIDE) * C4);
        #pragma unroll
        for (int i = 0; i < NACC; i++)
            m[i] = f4max(m[i], f4max(v[2 * i], v[2 * i + 1]));
    }
    for (; row < HW; row += STRIDE) {
        m[0] = f4max(m[0], __ldcs(base + (size_t)row * C4));
    }

    // Combine the 6 accumulators
    m[0] = f4max(m[0], m[1]);
    m[2] = f4max(m[2], m[3]);
    m[4] = f4max(m[4], m[5]);
    m[0] = f4max(m[0], f4max(m[2], m[4]));

    // Reduce across the 8 row-lanes sharing this c4 (tid, tid+32, ... tid+224)
    __shared__ float4 sm[THREADS];
    sm[threadIdx.x] = m[0];
    __syncthreads();
    if (threadIdx.x < 128) sm[threadIdx.x] = f4max(sm[threadIdx.x], sm[threadIdx.x + 128]);
    __syncthreads();
    if (threadIdx.x < 64)  sm[threadIdx.x] = f4max(sm[threadIdx.x], sm[threadIdx.x + 64]);
    __syncthreads();
    if (threadIdx.x < 32) {
        float4 v = f4max(sm[threadIdx.x], sm[threadIdx.x + 32]);
        float* o = out + b * C + threadIdx.x * 4;
        atomicMaxF(o + 0, v.x);
        atomicMaxF(o + 1, v.y);
        atomicMaxF(o + 2, v.z);
        atomicMaxF(o + 3, v.w);
    }
}

extern "C" void kernel_launch(void* const* d_in, const int* in_sizes, int n_in,
                              void* d_out, int out_size) {
    const float* in = (const float*)d_in[0];
    float* out = (float*)d_out;

    init_out_kernel<<<(out_size + 255) / 256, 256>>>(out, out_size);

    dim3 grid(GRID_X, B);
    max_spatial_kernel<<<grid, THREADS>>>(in, out);
}

// round 17
// speedup vs baseline: 1.0229x; 1.0035x over previous
#include <cuda_runtime.h>
#include <cuda_bf16.h>
#include <float.h>

// Problem: out[b][c] = max over (h,w) of in[b][h][w][c]
//   in : [32, 224, 224, 128] f32, NHWC (C contiguous)
//   out: [32, 128] f32
// Pure HBM-streaming reduction: 822 MB read, 16 KB written.
//
// FINAL (session winner; benches 118.8 / 119.3 / 119.3 / 119.3 / 119.8 us
// @ 87-89% DRAM, 6.9-7.0 TB/s): grid (37, 32) strided rows, occ 3 (80 regs)
// so 12 streaming LDG.128 are front-batched per thread (no staging), folded
// into 6 accumulators. smem tree reduce + float atomicMax into a
// -FLT_MAX-initialized output (separate init launch).
//
// Convergence evidence across 17 benches: occ {2,3,4} x MLP {4..16} x
// grid {608..1216} x {strided, contiguous, page-local} x {init+atomicMax,
// last-block-combine} all measure 6.6-7.0 TB/s; identical-source re-benches
// vary +-2.5us. occ 4 caps regs at 64 (load staging); occ 2 exposes
// warp-eligibility gaps; fused epilogue serializes the final combine.
// 822 MB at the ~7.0 TB/s practical HBM ceiling = ~117.5us floor; this
// kernel operates at >99% of it.

static constexpr int B  = 32;
static constexpr int HW = 224 * 224;   // 50176 spatial rows per batch
static constexpr int C  = 128;         // channels (contiguous)
static constexpr int C4 = C / 4;       // 32 float4 groups per row

static constexpr int THREADS = 256;    // 32 c4-lanes x 8 row-lanes
static constexpr int ROWS_PER_BLK = THREADS / C4;       // 8
static constexpr int GRID_X = 37;      // 37*32 = 1184 blocks
static constexpr int STRIDE = GRID_X * ROWS_PER_BLK;    // 296 rows
static constexpr int UNROLL = 12;      // loads front-batched per iteration
static constexpr int NACC   = 6;       // accumulators (fold pairs)

__device__ __forceinline__ float4 f4max(float4 a, float4 b) {
    return make_float4(fmaxf(a.x, b.x), fmaxf(a.y, b.y),
                       fmaxf(a.z, b.z), fmaxf(a.w, b.w));
}

// Float atomic-max via monotone int/uint reinterpretation (init = -FLT_MAX).
__device__ __forceinline__ void atomicMaxF(float* addr, float v) {
    if (v >= 0.0f) {
        atomicMax(reinterpret_cast<int*>(addr), __float_as_int(v));
    } else {
        atomicMin(reinterpret_cast<unsigned int*>(addr), __float_as_uint(v));
    }
}

__global__ void init_out_kernel(float* __restrict__ out, int n) {
    int i = blockIdx.x * blockDim.x + threadIdx.x;
    if (i < n) out[i] = -FLT_MAX;
}

__global__ __launch_bounds__(THREADS, 3)   // 80 regs: full 12-load batch
void max_spatial_kernel(const float* __restrict__ in, float* __restrict__ out) {
    const int b   = blockIdx.y;
    const int c4  = threadIdx.x & (C4 - 1);   // float4 channel group 0..31
    const int r   = threadIdx.x >> 5;         // row lane 0..7

    // Base pointer for this batch + channel group (float4 units)
    const float4* base =
        reinterpret_cast<const float4*>(in + (size_t)b * HW * C) + c4;

    int row = blockIdx.x * ROWS_PER_BLK + r;

    float4 m[NACC];
    #pragma unroll
    for (int i = 0; i < NACC; i++)
        m[i] = make_float4(-FLT_MAX, -FLT_MAX, -FLT_MAX, -FLT_MAX);

    // 12 independent streaming LDG.128 front-batched per iteration.
    for (; row + (UNROLL - 1) * STRIDE < HW; row += UNROLL * STRIDE) {
        float4 v[UNROLL];
        #pragma unroll
        for (int i = 0; i < UNROLL; i++)
            v[i] = __ldcs(base + (size_t)(row + i * STRIDE) * C4);
        #pragma unroll
        for (int i = 0; i < NACC; i++)
            m[i] = f4max(m[i], f4max(v[2 * i], v[2 * i + 1]));
    }
    for (; row < HW; row += STRIDE) {
        m[0] = f4max(m[0], __ldcs(base + (size_t)row * C4));
    }

    // Combine the 6 accumulators
    m[0] = f4max(m[0], m[1]);
    m[2] = f4max(m[2], m[3]);
    m[4] = f4max(m[4], m[5]);
    m[0] = f4max(m[0], f4max(m[2], m[4]));

    // Reduce across the 8 row-lanes sharing this c4 (tid, tid+32, ... tid+224)
    __shared__ float4 sm[THREADS];
    sm[threadIdx.x] = m[0];
    __syncthreads();
    if (threadIdx.x < 128) sm[threadIdx.x] = f4max(sm[threadIdx.x], sm[threadIdx.x + 128]);
    __syncthreads();
    if (threadIdx.x < 64)  sm[threadIdx.x] = f4max(sm[threadIdx.x], sm[threadIdx.x + 64]);
    __syncthreads();
    if (threadIdx.x < 32) {
        float4 v = f4max(sm[threadIdx.x], sm[threadIdx.x + 32]);
        float* o = out + b * C + threadIdx.x * 4;
        atomicMaxF(o + 0, v.x);
        atomicMaxF(o + 1, v.y);
        atomicMaxF(o + 2, v.z);
        atomicMaxF(o + 3, v.w);
    }
}

extern "C" void kernel_launch(void* const* d_in, const int* in_sizes, int n_in,
                              void* d_out, int out_size) {
    const float* in = (const float*)d_in[0];
    float* out = (float*)d_out;

    init_out_kernel<<<(out_size + 255) / 256, 256>>>(out, out_size);

    dim3 grid(GRID_X, B);
    max_spatial_kernel<<<grid, THREADS>>>(in, out);
}